// round 1
// baseline (speedup 1.0000x reference)
#include <cuda_runtime.h>
#include <math.h>

#define D_MODEL 768
#define NHEAD 12
#define HD 64
#define BATCH 2
#define SEQ 2048
#define MROWS (BATCH*SEQ)   // 4096

// -------- scratch (static device memory; no allocations) --------
__device__ float g_Q[BATCH*NHEAD*SEQ*HD];
__device__ float g_K[BATCH*NHEAD*SEQ*HD];
__device__ float g_V[BATCH*NHEAD*SEQ*HD];
__device__ float g_ctx[BATCH*SEQ*D_MODEL];

// ============================================================
// GEMM: out = X[M x 768] @ W[768 x 768] + bias
// tile 128x128x8, 256 threads, 8x8 per thread.
// scatter=1: write into [B,H,S,hd] head-major layout (QKV proj)
// scatter=0: write row-major [M x 768] (output proj / final out)
// ============================================================
__global__ __launch_bounds__(256) void gemm_kernel(
    const float* __restrict__ X, const float* __restrict__ W,
    const float* __restrict__ bias, float* __restrict__ out, int scatter)
{
    __shared__ float As[8][128];
    __shared__ float Bs[8][128];

    const int tid = threadIdx.x;
    const int tx = tid & 15;
    const int ty = tid >> 4;
    const int row0 = blockIdx.y * 128;
    const int col0 = blockIdx.x * 128;

    float acc[8][8];
#pragma unroll
    for (int i = 0; i < 8; i++)
#pragma unroll
        for (int j = 0; j < 8; j++) acc[i][j] = 0.f;

    const int am = tid >> 1;         // 0..127
    const int ak = (tid & 1) * 4;    // 0 or 4
    const int bk = tid >> 5;         // 0..7
    const int bn = (tid & 31) * 4;   // 0..124

    for (int k0 = 0; k0 < 768; k0 += 8) {
        float4 a = *(const float4*)&X[(size_t)(row0 + am) * 768 + k0 + ak];
        As[ak + 0][am] = a.x;
        As[ak + 1][am] = a.y;
        As[ak + 2][am] = a.z;
        As[ak + 3][am] = a.w;
        float4 b = *(const float4*)&W[(size_t)(k0 + bk) * 768 + col0 + bn];
        *(float4*)&Bs[bk][bn] = b;
        __syncthreads();

#pragma unroll
        for (int kk = 0; kk < 8; kk++) {
            float4 a0 = *(float4*)&As[kk][ty * 8];
            float4 a1 = *(float4*)&As[kk][ty * 8 + 4];
            float4 b0 = *(float4*)&Bs[kk][tx * 8];
            float4 b1 = *(float4*)&Bs[kk][tx * 8 + 4];
            float ar[8] = {a0.x, a0.y, a0.z, a0.w, a1.x, a1.y, a1.z, a1.w};
            float br[8] = {b0.x, b0.y, b0.z, b0.w, b1.x, b1.y, b1.z, b1.w};
#pragma unroll
            for (int i = 0; i < 8; i++)
#pragma unroll
                for (int j = 0; j < 8; j++)
                    acc[i][j] += ar[i] * br[j];
        }
        __syncthreads();
    }

    // epilogue
    const int ncol = col0 + tx * 8;
    float4 bv0 = *(const float4*)&bias[ncol];
    float4 bv1 = *(const float4*)&bias[ncol + 4];
    if (scatter) {
        // n -> (head, d); 8-wide column blocks never cross a 64-wide head
        const int h = ncol / HD;
        const int d = ncol % HD;
#pragma unroll
        for (int i = 0; i < 8; i++) {
            int m = row0 + ty * 8 + i;
            int bb = m / SEQ;
            int s = m % SEQ;
            size_t base = ((size_t)(bb * NHEAD + h) * SEQ + s) * HD + d;
            float4 o0, o1;
            o0.x = acc[i][0] + bv0.x; o0.y = acc[i][1] + bv0.y;
            o0.z = acc[i][2] + bv0.z; o0.w = acc[i][3] + bv0.w;
            o1.x = acc[i][4] + bv1.x; o1.y = acc[i][5] + bv1.y;
            o1.z = acc[i][6] + bv1.z; o1.w = acc[i][7] + bv1.w;
            *(float4*)&out[base] = o0;
            *(float4*)&out[base + 4] = o1;
        }
    } else {
#pragma unroll
        for (int i = 0; i < 8; i++) {
            int m = row0 + ty * 8 + i;
            size_t base = (size_t)m * 768 + ncol;
            float4 o0, o1;
            o0.x = acc[i][0] + bv0.x; o0.y = acc[i][1] + bv0.y;
            o0.z = acc[i][2] + bv0.z; o0.w = acc[i][3] + bv0.w;
            o1.x = acc[i][4] + bv1.x; o1.y = acc[i][5] + bv1.y;
            o1.z = acc[i][6] + bv1.z; o1.w = acc[i][7] + bv1.w;
            *(float4*)&out[base] = o0;
            *(float4*)&out[base + 4] = o1;
        }
    }
}

// ============================================================
// Flash attention: per (b,h) head, 128-query tile per block,
// iterate 64-key tiles with online softmax. fp32 throughout.
// ============================================================
#define LDK 68   // padded row length for KT / Vs / Ps

__global__ __launch_bounds__(256) void attn_kernel(
    const float* __restrict__ Qg, const float* __restrict__ Kg,
    const float* __restrict__ Vg, float* __restrict__ ctx)
{
    extern __shared__ float sm[];
    float* Qs = sm;                    // [128][64]
    float* KT = Qs + 128 * 64;         // [64][LDK]  KT[d][c] = K[c][d]
    float* Vs = KT + 64 * LDK;         // [64][LDK]  Vs[k][d]
    float* Ps = Vs + 64 * LDK;         // [128][LDK]

    const int tid = threadIdx.x;
    const int tx = tid & 15;
    const int ty = tid >> 4;
    const int bh = blockIdx.y;         // 0..B*H-1
    const int qt = blockIdx.x;         // 0..S/128-1

    const float* Qp = Qg + ((size_t)bh * SEQ + qt * 128) * HD;

    // load Q tile (layout identical -> flat float4 copy)
#pragma unroll
    for (int i = 0; i < 8; i++)
        ((float4*)Qs)[tid + 256 * i] = ((const float4*)Qp)[tid + 256 * i];

    float m[8], l[8], acc[8][4];
#pragma unroll
    for (int i = 0; i < 8; i++) {
        m[i] = -1e30f;
        l[i] = 0.f;
#pragma unroll
        for (int j = 0; j < 4; j++) acc[i][j] = 0.f;
    }

    const int kc = tid & 63;        // key index for KT load
    const int kd4 = tid >> 6;       // 0..3

    for (int kt = 0; kt < SEQ / 64; kt++) {
        const float* Kp = Kg + ((size_t)bh * SEQ + kt * 64) * HD;
        const float* Vp = Vg + ((size_t)bh * SEQ + kt * 64) * HD;
        __syncthreads();  // previous PV reads done before overwriting tiles

        // K tile -> transposed smem KT[d][c]
#pragma unroll
        for (int r = 0; r < 4; r++) {
            int d4 = kd4 + r * 4;                 // 0..15
            float4 kv = *(const float4*)&Kp[(size_t)kc * HD + d4 * 4];
            KT[(d4 * 4 + 0) * LDK + kc] = kv.x;
            KT[(d4 * 4 + 1) * LDK + kc] = kv.y;
            KT[(d4 * 4 + 2) * LDK + kc] = kv.z;
            KT[(d4 * 4 + 3) * LDK + kc] = kv.w;
        }
        // V tile -> Vs[k][d]
#pragma unroll
        for (int r = 0; r < 4; r++) {
            int idx = tid + 256 * r;              // 0..1023
            int vk = idx >> 4;
            int vd = (idx & 15) * 4;
            *(float4*)&Vs[vk * LDK + vd] = *(const float4*)&Vp[(size_t)vk * HD + vd];
        }
        __syncthreads();

        // scores: s[i][j] = Q[row][*] . K[col][*]
        float s[8][4];
#pragma unroll
        for (int i = 0; i < 8; i++)
#pragma unroll
            for (int j = 0; j < 4; j++) s[i][j] = 0.f;

#pragma unroll
        for (int d = 0; d < 64; d += 4) {
            float4 k0 = *(float4*)&KT[(d + 0) * LDK + tx * 4];
            float4 k1 = *(float4*)&KT[(d + 1) * LDK + tx * 4];
            float4 k2 = *(float4*)&KT[(d + 2) * LDK + tx * 4];
            float4 k3 = *(float4*)&KT[(d + 3) * LDK + tx * 4];
#pragma unroll
            for (int i = 0; i < 8; i++) {
                float4 q = *(float4*)&Qs[(ty * 8 + i) * 64 + d];
                s[i][0] += q.x * k0.x + q.y * k1.x + q.z * k2.x + q.w * k3.x;
                s[i][1] += q.x * k0.y + q.y * k1.y + q.z * k2.y + q.w * k3.y;
                s[i][2] += q.x * k0.z + q.y * k1.z + q.z * k2.z + q.w * k3.z;
                s[i][3] += q.x * k0.w + q.y * k1.w + q.z * k2.w + q.w * k3.w;
            }
        }

        // online softmax (per query row; 16 tx threads share a row)
        const float scale = 0.125f;  // 1/sqrt(64)
#pragma unroll
        for (int i = 0; i < 8; i++) {
            float mx = fmaxf(fmaxf(s[i][0], s[i][1]), fmaxf(s[i][2], s[i][3])) * scale;
#pragma unroll
            for (int off = 8; off >= 1; off >>= 1)
                mx = fmaxf(mx, __shfl_xor_sync(0xffffffffu, mx, off));
            float newm = fmaxf(m[i], mx);
            float corr = __expf(m[i] - newm);
            float ps = 0.f;
#pragma unroll
            for (int j = 0; j < 4; j++) {
                float p = __expf(s[i][j] * scale - newm);
                s[i][j] = p;
                ps += p;
            }
#pragma unroll
            for (int off = 8; off >= 1; off >>= 1)
                ps += __shfl_xor_sync(0xffffffffu, ps, off);
            l[i] = l[i] * corr + ps;
            m[i] = newm;
#pragma unroll
            for (int j = 0; j < 4; j++) acc[i][j] *= corr;
            float4 pv = make_float4(s[i][0], s[i][1], s[i][2], s[i][3]);
            *(float4*)&Ps[(ty * 8 + i) * LDK + tx * 4] = pv;
        }
        __syncthreads();

        // PV: acc[i][j] += P[row][k] * V[k][col]
#pragma unroll
        for (int k = 0; k < 64; k += 4) {
            float4 v0 = *(float4*)&Vs[(k + 0) * LDK + tx * 4];
            float4 v1 = *(float4*)&Vs[(k + 1) * LDK + tx * 4];
            float4 v2 = *(float4*)&Vs[(k + 2) * LDK + tx * 4];
            float4 v3 = *(float4*)&Vs[(k + 3) * LDK + tx * 4];
#pragma unroll
            for (int i = 0; i < 8; i++) {
                float4 p = *(float4*)&Ps[(ty * 8 + i) * LDK + k];
                acc[i][0] += p.x * v0.x + p.y * v1.x + p.z * v2.x + p.w * v3.x;
                acc[i][1] += p.x * v0.y + p.y * v1.y + p.z * v2.y + p.w * v3.y;
                acc[i][2] += p.x * v0.z + p.y * v1.z + p.z * v2.z + p.w * v3.z;
                acc[i][3] += p.x * v0.w + p.y * v1.w + p.z * v2.w + p.w * v3.w;
            }
        }
    }

    // epilogue: normalize and write context in [B,S,D] layout
    const int bb = bh / NHEAD;
    const int h = bh % NHEAD;
#pragma unroll
    for (int i = 0; i < 8; i++) {
        int q = qt * 128 + ty * 8 + i;
        float inv = 1.f / l[i];
        float4 o;
        o.x = acc[i][0] * inv;
        o.y = acc[i][1] * inv;
        o.z = acc[i][2] * inv;
        o.w = acc[i][3] * inv;
        *(float4*)&ctx[((size_t)(bb * SEQ) + q) * D_MODEL + h * HD + tx * 4] = o;
    }
}

// ============================================================
extern "C" void kernel_launch(void* const* d_in, const int* in_sizes, int n_in,
                              void* d_out, int out_size)
{
    const float* x  = (const float*)d_in[0];
    const float* Wq = (const float*)d_in[1];
    const float* bq = (const float*)d_in[2];
    const float* Wk = (const float*)d_in[3];
    const float* bk = (const float*)d_in[4];
    const float* Wv = (const float*)d_in[5];
    const float* bv = (const float*)d_in[6];
    const float* Wo = (const float*)d_in[7];
    const float* bo = (const float*)d_in[8];
    float* out = (float*)d_out;

    float *Qp, *Kp, *Vp, *ctxp;
    cudaGetSymbolAddress((void**)&Qp, g_Q);
    cudaGetSymbolAddress((void**)&Kp, g_K);
    cudaGetSymbolAddress((void**)&Vp, g_V);
    cudaGetSymbolAddress((void**)&ctxp, g_ctx);

    const size_t attn_smem = (size_t)(128 * 64 + 64 * LDK + 64 * LDK + 128 * LDK) * sizeof(float);
    cudaFuncSetAttribute(attn_kernel, cudaFuncAttributeMaxDynamicSharedMemorySize, (int)attn_smem);

    dim3 gg(768 / 128, MROWS / 128);   // (6, 32)
    gemm_kernel<<<gg, 256>>>(x, Wq, bq, Qp, 1);
    gemm_kernel<<<gg, 256>>>(x, Wk, bk, Kp, 1);
    gemm_kernel<<<gg, 256>>>(x, Wv, bv, Vp, 1);

    dim3 ga(SEQ / 128, BATCH * NHEAD); // (16, 24)
    attn_kernel<<<ga, 256, attn_smem>>>(Qp, Kp, Vp, ctxp);

    gemm_kernel<<<gg, 256>>>(ctxp, Wo, bo, out, 0);
}

// round 2
// speedup vs baseline: 3.0964x; 3.0964x over previous
#include <cuda_runtime.h>
#include <math.h>

#define D_MODEL 768
#define NHEAD 12
#define HD 64
#define BATCH 2
#define SEQ 2048
#define MROWS (BATCH*SEQ)   // 4096

// -------- scratch (static device memory; no allocations) --------
__device__ float g_Q[BATCH*NHEAD*SEQ*HD];
__device__ float g_K[BATCH*NHEAD*SEQ*HD];
__device__ float g_V[BATCH*NHEAD*SEQ*HD];
__device__ float g_ctx[BATCH*SEQ*D_MODEL];

// -------- tf32 helpers --------
__device__ __forceinline__ unsigned f2tf(float x) {
    unsigned r;
    asm("cvt.rna.tf32.f32 %0, %1;" : "=r"(r) : "f"(x));
    return r;
}
__device__ __forceinline__ uint4 f2tf4(float4 v) {
    uint4 r;
    r.x = f2tf(v.x); r.y = f2tf(v.y); r.z = f2tf(v.z); r.w = f2tf(v.w);
    return r;
}
// D = A(16x8 tf32) * B(8x8 tf32) + D, fp32 accum
__device__ __forceinline__ void mma8(float* c, const unsigned* a, unsigned b0, unsigned b1) {
    asm volatile(
        "mma.sync.aligned.m16n8k8.row.col.f32.tf32.tf32.f32 "
        "{%0,%1,%2,%3},{%4,%5,%6,%7},{%8,%9},{%0,%1,%2,%3};"
        : "+f"(c[0]), "+f"(c[1]), "+f"(c[2]), "+f"(c[3])
        : "r"(a[0]), "r"(a[1]), "r"(a[2]), "r"(a[3]), "r"(b0), "r"(b1));
}

// ============================================================
// tf32 GEMM: out = X[M x 768] @ W[768 x 768] + bias
// block 128x128, k-slab 32, 256 threads = 8 warps (4m x 2n),
// warp-tile 32m x 64n via m16n8k8.
// ============================================================
#define ALD 36    // 36 % 32 == 4 -> A-frag banks 4g+t conflict-free
#define BLD 136   // 136 % 32 == 8 -> B-frag banks 8t+g conflict-free

__global__ __launch_bounds__(256) void gemm_tf32(
    const float* __restrict__ X, const float* __restrict__ W,
    const float* __restrict__ bias, float* __restrict__ out, int scatter)
{
    __shared__ unsigned As[128 * ALD];   // [m][k], 18KB
    __shared__ unsigned Bs[32 * BLD];    // [k][n], 17.4KB

    const int tid = threadIdx.x;
    const int lane = tid & 31;
    const int g = lane >> 2;      // 0..7
    const int t = lane & 3;       // 0..3
    const int wid = tid >> 5;
    const int wm = (wid & 3) * 32;    // warp m offset
    const int wn = (wid >> 2) * 64;   // warp n offset
    const int row0 = blockIdx.y * 128;
    const int col0 = blockIdx.x * 128;

    float acc[2][8][4];
#pragma unroll
    for (int i = 0; i < 2; i++)
#pragma unroll
        for (int j = 0; j < 8; j++)
#pragma unroll
            for (int k = 0; k < 4; k++) acc[i][j][k] = 0.f;

    for (int k0 = 0; k0 < 768; k0 += 32) {
        // load A slab 128x32
#pragma unroll
        for (int r = 0; r < 4; r++) {
            int idx = tid + 256 * r;
            int m = idx >> 3;
            int kq = (idx & 7) * 4;
            float4 v = *(const float4*)&X[(size_t)(row0 + m) * 768 + k0 + kq];
            *(uint4*)&As[m * ALD + kq] = f2tf4(v);
        }
        // load B slab 32x128
#pragma unroll
        for (int r = 0; r < 4; r++) {
            int idx = tid + 256 * r;
            int k = idx >> 5;
            int nq = (idx & 31) * 4;
            float4 v = *(const float4*)&W[(size_t)(k0 + k) * 768 + col0 + nq];
            *(uint4*)&Bs[k * BLD + nq] = f2tf4(v);
        }
        __syncthreads();

#pragma unroll
        for (int ks = 0; ks < 4; ks++) {
            const int kc = ks * 8 + t;
            unsigned a[2][4];
#pragma unroll
            for (int mt = 0; mt < 2; mt++) {
                int r0 = wm + mt * 16 + g;
                a[mt][0] = As[r0 * ALD + kc];
                a[mt][1] = As[(r0 + 8) * ALD + kc];
                a[mt][2] = As[r0 * ALD + kc + 4];
                a[mt][3] = As[(r0 + 8) * ALD + kc + 4];
            }
#pragma unroll
            for (int nt = 0; nt < 8; nt++) {
                int cb = wn + nt * 8 + g;
                unsigned b0 = Bs[kc * BLD + cb];
                unsigned b1 = Bs[(kc + 4) * BLD + cb];
                mma8(acc[0][nt], a[0], b0, b1);
                mma8(acc[1][nt], a[1], b0, b1);
            }
        }
        __syncthreads();
    }

    // epilogue: C frag c0:[g][2t], c1:[g][2t+1], c2:[g+8][2t], c3:[g+8][2t+1]
#pragma unroll
    for (int nt = 0; nt < 8; nt++) {
        int col = col0 + wn + nt * 8 + 2 * t;
        float b0 = bias[col], b1 = bias[col + 1];
#pragma unroll
        for (int mt = 0; mt < 2; mt++) {
#pragma unroll
            for (int hh = 0; hh < 2; hh++) {
                int m = row0 + wm + mt * 16 + g + hh * 8;
                float2 o;
                o.x = acc[mt][nt][hh * 2] + b0;
                o.y = acc[mt][nt][hh * 2 + 1] + b1;
                if (scatter) {
                    int hd_ = col >> 6;      // head
                    int d = col & 63;
                    int bb = m >> 11;        // /SEQ
                    int s = m & 2047;
                    *(float2*)&out[((size_t)(bb * NHEAD + hd_) * SEQ + s) * HD + d] = o;
                } else {
                    *(float2*)&out[(size_t)m * 768 + col] = o;
                }
            }
        }
    }
}

// ============================================================
// tf32 flash attention: 128-q tile per block, 4 warps x 32q,
// 64-key tiles, online softmax on mma C-fragments.
// ============================================================
#define QLD 68   // 68%32==4: A-frag pattern
#define KLD 68   // K B-frag reads [key][d]: (n+g)*KLD + k+t -> 4g+t ok
#define VLD 72   // V B-frag reads [key][d] as B[k][n]: (k+t)*VLD + n+g -> 8t+g ok
#define PLD 68

__global__ __launch_bounds__(128) void attn_tf32(
    const float* __restrict__ Qg, const float* __restrict__ Kg,
    const float* __restrict__ Vg, float* __restrict__ ctx)
{
    extern __shared__ unsigned sm[];
    unsigned* Qs = sm;                     // [128][QLD]
    unsigned* Ks = Qs + 128 * QLD;         // [64][KLD]
    unsigned* Vs = Ks + 64 * KLD;          // [64][VLD]
    unsigned* Ps = Vs + 64 * VLD;          // [128][PLD]

    const int tid = threadIdx.x;
    const int lane = tid & 31;
    const int g = lane >> 2;
    const int t = lane & 3;
    const int wid = tid >> 5;          // 0..3
    const int qb = wid * 32;           // warp q offset in tile
    const int bh = blockIdx.y;
    const int qt = blockIdx.x;

    const float* Qp = Qg + ((size_t)bh * SEQ + qt * 128) * HD;

    // load Q tile (tf32)
#pragma unroll
    for (int r = 0; r < 16; r++) {
        int idx = tid + 128 * r;
        int q = idx >> 4;
        int d4 = (idx & 15) * 4;
        float4 v = *(const float4*)&Qp[(size_t)q * HD + d4];
        *(uint4*)&Qs[q * QLD + d4] = f2tf4(v);
    }

    float acc[2][8][4];
    float rowm[2][2], rowl[2][2];
#pragma unroll
    for (int i = 0; i < 2; i++) {
#pragma unroll
        for (int j = 0; j < 2; j++) { rowm[i][j] = -1e30f; rowl[i][j] = 0.f; }
#pragma unroll
        for (int j = 0; j < 8; j++)
#pragma unroll
            for (int k = 0; k < 4; k++) acc[i][j][k] = 0.f;
    }

    const float scale = 0.125f;   // 1/sqrt(64)

    for (int kt = 0; kt < SEQ / 64; kt++) {
        const float* Kp = Kg + ((size_t)bh * SEQ + kt * 64) * HD;
        const float* Vp = Vg + ((size_t)bh * SEQ + kt * 64) * HD;
        __syncthreads();   // previous iteration's Ks/Vs reads complete

        // load K,V tiles (natural [key][d] layout, tf32)
#pragma unroll
        for (int r = 0; r < 8; r++) {
            int idx = tid + 128 * r;
            int key = idx >> 4;
            int d4 = (idx & 15) * 4;
            float4 kv = *(const float4*)&Kp[(size_t)key * HD + d4];
            *(uint4*)&Ks[key * KLD + d4] = f2tf4(kv);
            float4 vv = *(const float4*)&Vp[(size_t)key * HD + d4];
            *(uint4*)&Vs[key * VLD + d4] = f2tf4(vv);
        }
        __syncthreads();

        // ---- scores = Q @ K^T : warp computes 32q x 64key ----
        float sc[2][8][4];
#pragma unroll
        for (int i = 0; i < 2; i++)
#pragma unroll
            for (int j = 0; j < 8; j++)
#pragma unroll
                for (int k = 0; k < 4; k++) sc[i][j][k] = 0.f;

#pragma unroll
        for (int ks = 0; ks < 8; ks++) {
            const int kc = ks * 8 + t;
            unsigned a[2][4];
#pragma unroll
            for (int mt = 0; mt < 2; mt++) {
                int r0 = qb + mt * 16 + g;
                a[mt][0] = Qs[r0 * QLD + kc];
                a[mt][1] = Qs[(r0 + 8) * QLD + kc];
                a[mt][2] = Qs[r0 * QLD + kc + 4];
                a[mt][3] = Qs[(r0 + 8) * QLD + kc + 4];
            }
#pragma unroll
            for (int nt = 0; nt < 8; nt++) {
                // B[k=d][n=key] = K[key][d]
                unsigned b0 = Ks[(nt * 8 + g) * KLD + kc];
                unsigned b1 = Ks[(nt * 8 + g) * KLD + kc + 4];
                mma8(sc[0][nt], a[0], b0, b1);
                mma8(sc[1][nt], a[1], b0, b1);
            }
        }

        // ---- online softmax per row (row = 4 lanes sharing g) ----
#pragma unroll
        for (int mt = 0; mt < 2; mt++) {
#pragma unroll
            for (int hh = 0; hh < 2; hh++) {
                float mx = -1e30f;
#pragma unroll
                for (int nt = 0; nt < 8; nt++)
                    mx = fmaxf(mx, fmaxf(sc[mt][nt][hh * 2], sc[mt][nt][hh * 2 + 1]));
                mx = fmaxf(mx, __shfl_xor_sync(0xffffffffu, mx, 1));
                mx = fmaxf(mx, __shfl_xor_sync(0xffffffffu, mx, 2));
                float newm = fmaxf(rowm[mt][hh], mx);
                float corr = __expf((rowm[mt][hh] - newm) * scale);
                rowm[mt][hh] = newm;
                float ps = 0.f;
#pragma unroll
                for (int nt = 0; nt < 8; nt++) {
                    float p0 = __expf((sc[mt][nt][hh * 2]     - newm) * scale);
                    float p1 = __expf((sc[mt][nt][hh * 2 + 1] - newm) * scale);
                    sc[mt][nt][hh * 2] = p0;
                    sc[mt][nt][hh * 2 + 1] = p1;
                    ps += p0 + p1;
                }
                ps += __shfl_xor_sync(0xffffffffu, ps, 1);
                ps += __shfl_xor_sync(0xffffffffu, ps, 2);
                rowl[mt][hh] = rowl[mt][hh] * corr + ps;
#pragma unroll
                for (int nt = 0; nt < 8; nt++) {
                    acc[mt][nt][hh * 2] *= corr;
                    acc[mt][nt][hh * 2 + 1] *= corr;
                }
                // write P (tf32) to smem: rows own warp only
                int row = qb + mt * 16 + g + hh * 8;
#pragma unroll
                for (int nt = 0; nt < 8; nt++) {
                    uint2 pp;
                    pp.x = f2tf(sc[mt][nt][hh * 2]);
                    pp.y = f2tf(sc[mt][nt][hh * 2 + 1]);
                    *(uint2*)&Ps[row * PLD + nt * 8 + 2 * t] = pp;
                }
            }
        }
        __syncwarp();

        // ---- acc += P @ V : warp computes 32q x 64d ----
#pragma unroll
        for (int ks = 0; ks < 8; ks++) {
            const int kc = ks * 8 + t;
            unsigned a[2][4];
#pragma unroll
            for (int mt = 0; mt < 2; mt++) {
                int r0 = qb + mt * 16 + g;
                a[mt][0] = Ps[r0 * PLD + kc];
                a[mt][1] = Ps[(r0 + 8) * PLD + kc];
                a[mt][2] = Ps[r0 * PLD + kc + 4];
                a[mt][3] = Ps[(r0 + 8) * PLD + kc + 4];
            }
#pragma unroll
            for (int nt = 0; nt < 8; nt++) {
                // B[k=key][n=d] = V[key][d]
                unsigned b0 = Vs[kc * VLD + nt * 8 + g];
                unsigned b1 = Vs[(kc + 4) * VLD + nt * 8 + g];
                mma8(acc[0][nt], a[0], b0, b1);
                mma8(acc[1][nt], a[1], b0, b1);
            }
        }
    }

    // ---- epilogue: normalize, write [B,S,D] ----
    const int bb = bh / NHEAD;
    const int head = bh % NHEAD;
#pragma unroll
    for (int mt = 0; mt < 2; mt++) {
#pragma unroll
        for (int hh = 0; hh < 2; hh++) {
            int q = qt * 128 + qb + mt * 16 + g + hh * 8;
            float inv = 1.f / rowl[mt][hh];
#pragma unroll
            for (int nt = 0; nt < 8; nt++) {
                int d = nt * 8 + 2 * t;
                float2 o;
                o.x = acc[mt][nt][hh * 2] * inv;
                o.y = acc[mt][nt][hh * 2 + 1] * inv;
                *(float2*)&ctx[((size_t)(bb * SEQ) + q) * D_MODEL + head * HD + d] = o;
            }
        }
    }
}

// ============================================================
extern "C" void kernel_launch(void* const* d_in, const int* in_sizes, int n_in,
                              void* d_out, int out_size)
{
    const float* x  = (const float*)d_in[0];
    const float* Wq = (const float*)d_in[1];
    const float* bq = (const float*)d_in[2];
    const float* Wk = (const float*)d_in[3];
    const float* bk = (const float*)d_in[4];
    const float* Wv = (const float*)d_in[5];
    const float* bv = (const float*)d_in[6];
    const float* Wo = (const float*)d_in[7];
    const float* bo = (const float*)d_in[8];
    float* out = (float*)d_out;

    float *Qp, *Kp, *Vp, *ctxp;
    cudaGetSymbolAddress((void**)&Qp, g_Q);
    cudaGetSymbolAddress((void**)&Kp, g_K);
    cudaGetSymbolAddress((void**)&Vp, g_V);
    cudaGetSymbolAddress((void**)&ctxp, g_ctx);

    const size_t attn_smem =
        (size_t)(128 * QLD + 64 * KLD + 64 * VLD + 128 * PLD) * sizeof(unsigned);
    cudaFuncSetAttribute(attn_tf32, cudaFuncAttributeMaxDynamicSharedMemorySize,
                         (int)attn_smem);

    dim3 gg(768 / 128, MROWS / 128);   // (6, 32)
    gemm_tf32<<<gg, 256>>>(x, Wq, bq, Qp, 1);
    gemm_tf32<<<gg, 256>>>(x, Wk, bk, Kp, 1);
    gemm_tf32<<<gg, 256>>>(x, Wv, bv, Vp, 1);

    dim3 ga(SEQ / 128, BATCH * NHEAD); // (16, 24)
    attn_tf32<<<ga, 128, attn_smem>>>(Qp, Kp, Vp, ctxp);

    gemm_tf32<<<gg, 256>>>(ctxp, Wo, bo, out, 0);
}

// round 3
// speedup vs baseline: 5.1660x; 1.6684x over previous
#include <cuda_runtime.h>
#include <cuda_fp16.h>
#include <math.h>

#define D_MODEL 768
#define NHEAD 12
#define HD 64
#define BATCH 2
#define SEQ 2048
#define MROWS (BATCH*SEQ)   // 4096

// -------- scratch (fp16; no allocations) --------
__device__ __half g_Q[BATCH*NHEAD*SEQ*HD];
__device__ __half g_K[BATCH*NHEAD*SEQ*HD];
__device__ __half g_V[BATCH*NHEAD*SEQ*HD];
__device__ __half g_ctx[MROWS*D_MODEL];

// -------- helpers --------
__device__ __forceinline__ unsigned smem_u32(const void* p) {
    return (unsigned)__cvta_generic_to_shared(p);
}
__device__ __forceinline__ unsigned pack2(float a, float b) {
    __half2 h = __floats2half2_rn(a, b);
    return *reinterpret_cast<unsigned*>(&h);
}
__device__ __forceinline__ void ldm4(unsigned& r0, unsigned& r1, unsigned& r2, unsigned& r3,
                                     unsigned addr) {
    asm volatile("ldmatrix.sync.aligned.m8n8.x4.shared.b16 {%0,%1,%2,%3},[%4];"
                 : "=r"(r0), "=r"(r1), "=r"(r2), "=r"(r3) : "r"(addr));
}
__device__ __forceinline__ void ldm4t(unsigned& r0, unsigned& r1, unsigned& r2, unsigned& r3,
                                      unsigned addr) {
    asm volatile("ldmatrix.sync.aligned.m8n8.x4.trans.shared.b16 {%0,%1,%2,%3},[%4];"
                 : "=r"(r0), "=r"(r1), "=r"(r2), "=r"(r3) : "r"(addr));
}
// D(16x8 f32) += A(16x16 f16) * B(16x8 f16)
__device__ __forceinline__ void mma16816(float* c, const unsigned* a, unsigned b0, unsigned b1) {
    asm volatile(
        "mma.sync.aligned.m16n8k16.row.col.f32.f16.f16.f32 "
        "{%0,%1,%2,%3},{%4,%5,%6,%7},{%8,%9},{%0,%1,%2,%3};"
        : "+f"(c[0]), "+f"(c[1]), "+f"(c[2]), "+f"(c[3])
        : "r"(a[0]), "r"(a[1]), "r"(a[2]), "r"(a[3]), "r"(b0), "r"(b1));
}
__device__ __forceinline__ void cp16(unsigned dst, const void* src) {
    asm volatile("cp.async.cg.shared.global [%0], [%1], 16;" :: "r"(dst), "l"(src));
}
__device__ __forceinline__ void cp_commit() { asm volatile("cp.async.commit_group;"); }
__device__ __forceinline__ void cp_wait1() { asm volatile("cp.async.wait_group 1;"); }
__device__ __forceinline__ void cp_wait0() { asm volatile("cp.async.wait_group 0;"); }

// ============================================================
// fp16 GEMM: out = X[M x 768] @ W[768 x 768] + bias, (+scale)
// block 64m x 128n, k-slab 32, 256 thr = 8 warps (2m x 4n),
// warp tile 32m x 32n via m16n8k16 + ldmatrix.
// ============================================================
#define ALD 40    // halves; 80B row stride -> ldmatrix conflict-free
#define BLD 136   // halves; 272B row stride -> conflict-free

template<typename TA, bool OUT_HALF, bool SCATTER>
__global__ __launch_bounds__(256) void gemm_f16(
    const TA* __restrict__ X, const float* __restrict__ W,
    const float* __restrict__ bias, void* __restrict__ outp, float oscale)
{
    __shared__ __half As[64 * ALD];
    __shared__ __half Bs[32 * BLD];

    const int tid = threadIdx.x;
    const int lane = tid & 31;
    const int g = lane >> 2;
    const int t = lane & 3;
    const int wid = tid >> 5;
    const int wm = (wid & 1) * 32;
    const int wn = (wid >> 1) * 32;
    const int row0 = blockIdx.y * 64;
    const int col0 = blockIdx.x * 128;

    float acc[2][4][4];
#pragma unroll
    for (int i = 0; i < 2; i++)
#pragma unroll
        for (int j = 0; j < 4; j++)
#pragma unroll
            for (int k = 0; k < 4; k++) acc[i][j][k] = 0.f;

    const int ar = tid >> 2;             // 0..63
    const int akc = (tid & 3) * 8;       // 0,8,16,24
    const int br = tid >> 3;             // 0..31
    const int bnc = (tid & 7) * 16;      // 0..112

    for (int k0 = 0; k0 < 768; k0 += 32) {
        // ---- stage A (convert to half if needed) ----
        if constexpr (sizeof(TA) == 4) {
            const float* Xf = (const float*)X;
            float4 v0 = *(const float4*)&Xf[(size_t)(row0 + ar) * 768 + k0 + akc];
            float4 v1 = *(const float4*)&Xf[(size_t)(row0 + ar) * 768 + k0 + akc + 4];
            uint4 h;
            h.x = pack2(v0.x, v0.y); h.y = pack2(v0.z, v0.w);
            h.z = pack2(v1.x, v1.y); h.w = pack2(v1.z, v1.w);
            *(uint4*)&As[ar * ALD + akc] = h;
        } else {
            const __half* Xh = (const __half*)X;
            *(uint4*)&As[ar * ALD + akc] =
                *(const uint4*)&Xh[(size_t)(row0 + ar) * 768 + k0 + akc];
        }
        // ---- stage B (fp32 W -> half), natural [k][n] ----
        {
            const float* src = &W[(size_t)(k0 + br) * 768 + col0 + bnc];
            float4 w0 = *(const float4*)&src[0];
            float4 w1 = *(const float4*)&src[4];
            float4 w2 = *(const float4*)&src[8];
            float4 w3 = *(const float4*)&src[12];
            uint4 h0, h1;
            h0.x = pack2(w0.x, w0.y); h0.y = pack2(w0.z, w0.w);
            h0.z = pack2(w1.x, w1.y); h0.w = pack2(w1.z, w1.w);
            h1.x = pack2(w2.x, w2.y); h1.y = pack2(w2.z, w2.w);
            h1.z = pack2(w3.x, w3.y); h1.w = pack2(w3.z, w3.w);
            *(uint4*)&Bs[br * BLD + bnc] = h0;
            *(uint4*)&Bs[br * BLD + bnc + 8] = h1;
        }
        __syncthreads();

#pragma unroll
        for (int ks = 0; ks < 2; ks++) {
            unsigned a[2][4];
#pragma unroll
            for (int mt = 0; mt < 2; mt++)
                ldm4(a[mt][0], a[mt][1], a[mt][2], a[mt][3],
                     smem_u32(&As[(wm + mt * 16 + (lane & 15)) * ALD +
                                  ks * 16 + ((lane >> 4) << 3)]));
            unsigned b[2][4];
#pragma unroll
            for (int np = 0; np < 2; np++)
                ldm4t(b[np][0], b[np][1], b[np][2], b[np][3],
                      smem_u32(&Bs[(ks * 16 + (lane & 7) + ((lane >> 3) & 1) * 8) * BLD +
                                   wn + np * 16 + (lane >> 4) * 8]));
#pragma unroll
            for (int mt = 0; mt < 2; mt++)
#pragma unroll
                for (int np = 0; np < 2; np++) {
                    mma16816(acc[mt][np * 2], a[mt], b[np][0], b[np][1]);
                    mma16816(acc[mt][np * 2 + 1], a[mt], b[np][2], b[np][3]);
                }
        }
        __syncthreads();
    }

    // ---- epilogue ----
#pragma unroll
    for (int nt = 0; nt < 4; nt++) {
        int col = col0 + wn + nt * 8 + 2 * t;
        float b0 = bias[col], b1 = bias[col + 1];
#pragma unroll
        for (int mt = 0; mt < 2; mt++)
#pragma unroll
            for (int hh = 0; hh < 2; hh++) {
                int m = row0 + wm + mt * 16 + g + hh * 8;
                float v0 = (acc[mt][nt][hh * 2] + b0) * oscale;
                float v1 = (acc[mt][nt][hh * 2 + 1] + b1) * oscale;
                if constexpr (OUT_HALF) {
                    __half* oh = (__half*)outp;
                    size_t idx;
                    if constexpr (SCATTER) {
                        int head = col >> 6, d = col & 63;
                        int bb = m >> 11, s = m & 2047;
                        idx = ((size_t)(bb * NHEAD + head) * SEQ + s) * HD + d;
                    } else {
                        idx = (size_t)m * 768 + col;
                    }
                    *(__half2*)&oh[idx] = __floats2half2_rn(v0, v1);
                } else {
                    float* of = (float*)outp;
                    float2 o; o.x = v0; o.y = v1;
                    *(float2*)&of[(size_t)m * 768 + col] = o;
                }
            }
    }
}

// ============================================================
// fp16 flash attention: q-tile 128, 8 warps x 16 q-rows,
// 64-key iterations, Q & P register-resident,
// K/V double-buffered via cp.async.
// ============================================================
#define QLD 72
#define KVLD 72

__global__ __launch_bounds__(256) void attn_f16(
    const __half* __restrict__ Qg, const __half* __restrict__ Kg,
    const __half* __restrict__ Vg, __half* __restrict__ ctx)
{
    extern __shared__ __half sm[];
    __half* Qs = sm;                       // [128][QLD]
    __half* KV = sm + 128 * QLD;           // 2 stages x (K[64][KVLD], V[64][KVLD])

    const int tid = threadIdx.x;
    const int lane = tid & 31;
    const int g = lane >> 2;
    const int t = lane & 3;
    const int wid = tid >> 5;           // 0..7
    const int qr = wid * 16;            // warp q-row offset
    const int bh = blockIdx.y;
    const int qt = blockIdx.x;

    const __half* Qp = Qg + ((size_t)bh * SEQ + qt * 128) * HD;
    const __half* Kbase = Kg + (size_t)bh * SEQ * HD;
    const __half* Vbase = Vg + (size_t)bh * SEQ * HD;

    // ---- stage Q tile, then load Q fragments to registers ----
#pragma unroll
    for (int i = 0; i < 4; i++) {
        int ci = tid + 256 * i;          // 1024 chunks of 8 halves
        int row = ci >> 3, c = ci & 7;
        *(uint4*)&Qs[row * QLD + c * 8] = *(const uint4*)&Qp[(size_t)row * HD + c * 8];
    }
    __syncthreads();
    unsigned qa[4][4];
#pragma unroll
    for (int ks = 0; ks < 4; ks++)
        ldm4(qa[ks][0], qa[ks][1], qa[ks][2], qa[ks][3],
             smem_u32(&Qs[(qr + (lane & 15)) * QLD + ks * 16 + ((lane >> 4) << 3)]));

    float acc[8][4];
    float rowm[2] = {-1e30f, -1e30f}, rowl[2] = {0.f, 0.f};
#pragma unroll
    for (int i = 0; i < 8; i++)
#pragma unroll
        for (int j = 0; j < 4; j++) acc[i][j] = 0.f;

    const int NT = SEQ / 64;

    // submit K/V tile kt into stage st
    auto submit = [&](int kt, int st) {
        const __half* Kp = Kbase + (size_t)kt * 64 * HD;
        const __half* Vp = Vbase + (size_t)kt * 64 * HD;
        __half* Kd = KV + st * 2 * 64 * KVLD;
        __half* Vd = Kd + 64 * KVLD;
#pragma unroll
        for (int i = 0; i < 2; i++) {
            int ci = tid + 256 * i;      // 512 chunks
            int row = ci >> 3, c = ci & 7;
            cp16(smem_u32(&Kd[row * KVLD + c * 8]), &Kp[(size_t)row * HD + c * 8]);
            cp16(smem_u32(&Vd[row * KVLD + c * 8]), &Vp[(size_t)row * HD + c * 8]);
        }
        cp_commit();
    };

    submit(0, 0);

    for (int kt = 0; kt < NT; kt++) {
        const int s = kt & 1;
        if (kt > 0) __syncthreads();          // all warps done with stage s (reused now)
        if (kt + 1 < NT) { submit(kt + 1, s ^ 1); cp_wait1(); }
        else cp_wait0();
        __syncthreads();

        const __half* Kd = KV + s * 2 * 64 * KVLD;
        const __half* Vd = Kd + 64 * KVLD;

        // ---- scores = Q @ K^T (16q x 64key per warp) ----
        float sc[8][4];
#pragma unroll
        for (int i = 0; i < 8; i++)
#pragma unroll
            for (int j = 0; j < 4; j++) sc[i][j] = 0.f;

#pragma unroll
        for (int ks = 0; ks < 4; ks++) {
            unsigned kb[4][4];
#pragma unroll
            for (int kp = 0; kp < 4; kp++)
                ldm4(kb[kp][0], kb[kp][1], kb[kp][2], kb[kp][3],
                     smem_u32(&Kd[(kp * 16 + (lane & 15)) * KVLD +
                                  ks * 16 + ((lane >> 4) << 3)]));
#pragma unroll
            for (int kp = 0; kp < 4; kp++) {
                mma16816(sc[kp * 2],     qa[ks], kb[kp][0], kb[kp][2]);
                mma16816(sc[kp * 2 + 1], qa[ks], kb[kp][1], kb[kp][3]);
            }
        }

        // ---- online softmax (scale folded into Q) ----
#pragma unroll
        for (int hh = 0; hh < 2; hh++) {
            float mx = -1e30f;
#pragma unroll
            for (int nt = 0; nt < 8; nt++)
                mx = fmaxf(mx, fmaxf(sc[nt][hh * 2], sc[nt][hh * 2 + 1]));
            mx = fmaxf(mx, __shfl_xor_sync(0xffffffffu, mx, 1));
            mx = fmaxf(mx, __shfl_xor_sync(0xffffffffu, mx, 2));
            float newm = fmaxf(rowm[hh], mx);
            float corr = __expf(rowm[hh] - newm);
            rowm[hh] = newm;
            float ps = 0.f;
#pragma unroll
            for (int nt = 0; nt < 8; nt++) {
                float p0 = __expf(sc[nt][hh * 2] - newm);
                float p1 = __expf(sc[nt][hh * 2 + 1] - newm);
                sc[nt][hh * 2] = p0;
                sc[nt][hh * 2 + 1] = p1;
                ps += p0 + p1;
            }
            ps += __shfl_xor_sync(0xffffffffu, ps, 1);
            ps += __shfl_xor_sync(0xffffffffu, ps, 2);
            rowl[hh] = rowl[hh] * corr + ps;
#pragma unroll
            for (int nt = 0; nt < 8; nt++) {
                acc[nt][hh * 2] *= corr;
                acc[nt][hh * 2 + 1] *= corr;
            }
        }

        // ---- P: C-fragment -> A-fragment, register-direct ----
        unsigned ph[4][4];
#pragma unroll
        for (int ks = 0; ks < 4; ks++) {
            ph[ks][0] = pack2(sc[2 * ks][0],     sc[2 * ks][1]);
            ph[ks][1] = pack2(sc[2 * ks][2],     sc[2 * ks][3]);
            ph[ks][2] = pack2(sc[2 * ks + 1][0], sc[2 * ks + 1][1]);
            ph[ks][3] = pack2(sc[2 * ks + 1][2], sc[2 * ks + 1][3]);
        }

        // ---- acc += P @ V (16q x 64d per warp) ----
#pragma unroll
        for (int ks = 0; ks < 4; ks++) {
            unsigned vb[4][4];
#pragma unroll
            for (int dp = 0; dp < 4; dp++)
                ldm4t(vb[dp][0], vb[dp][1], vb[dp][2], vb[dp][3],
                      smem_u32(&Vd[(ks * 16 + (lane & 7) + ((lane >> 3) & 1) * 8) * KVLD +
                                   dp * 16 + (lane >> 4) * 8]));
#pragma unroll
            for (int dp = 0; dp < 4; dp++) {
                mma16816(acc[dp * 2],     ph[ks], vb[dp][0], vb[dp][1]);
                mma16816(acc[dp * 2 + 1], ph[ks], vb[dp][2], vb[dp][3]);
            }
        }
    }

    // ---- epilogue: normalize, write half ctx in [B,S,D] ----
    const int bb = bh / NHEAD;
    const int head = bh % NHEAD;
#pragma unroll
    for (int hh = 0; hh < 2; hh++) {
        int q = qt * 128 + qr + g + hh * 8;
        float inv = 1.f / rowl[hh];
#pragma unroll
        for (int nt = 0; nt < 8; nt++) {
            int d = nt * 8 + 2 * t;
            *(__half2*)&ctx[(size_t)(bb * SEQ + q) * D_MODEL + head * HD + d] =
                __floats2half2_rn(acc[nt][hh * 2] * inv, acc[nt][hh * 2 + 1] * inv);
        }
    }
}

// ============================================================
extern "C" void kernel_launch(void* const* d_in, const int* in_sizes, int n_in,
                              void* d_out, int out_size)
{
    const float* x  = (const float*)d_in[0];
    const float* Wq = (const float*)d_in[1];
    const float* bq = (const float*)d_in[2];
    const float* Wk = (const float*)d_in[3];
    const float* bk = (const float*)d_in[4];
    const float* Wv = (const float*)d_in[5];
    const float* bv = (const float*)d_in[6];
    const float* Wo = (const float*)d_in[7];
    const float* bo = (const float*)d_in[8];
    float* out = (float*)d_out;

    __half *Qp, *Kp, *Vp, *ctxp;
    cudaGetSymbolAddress((void**)&Qp, g_Q);
    cudaGetSymbolAddress((void**)&Kp, g_K);
    cudaGetSymbolAddress((void**)&Vp, g_V);
    cudaGetSymbolAddress((void**)&ctxp, g_ctx);

    const size_t attn_smem = (size_t)(128 * QLD + 4 * 64 * KVLD) * sizeof(__half);
    cudaFuncSetAttribute(attn_f16, cudaFuncAttributeMaxDynamicSharedMemorySize,
                         (int)attn_smem);

    dim3 gg(768 / 128, MROWS / 64);    // (6, 64)
    // scale 1/sqrt(hd) folded into Q projection
    gemm_f16<float, true, true><<<gg, 256>>>(x, Wq, bq, Qp, 0.125f);
    gemm_f16<float, true, true><<<gg, 256>>>(x, Wk, bk, Kp, 1.0f);
    gemm_f16<float, true, true><<<gg, 256>>>(x, Wv, bv, Vp, 1.0f);

    dim3 ga(SEQ / 128, BATCH * NHEAD); // (16, 24)
    attn_f16<<<ga, 256, attn_smem>>>(Qp, Kp, Vp, ctxp);

    gemm_f16<__half, false, false><<<gg, 256>>>(ctxp, Wo, bo, out, 1.0f);
}

// round 4
// speedup vs baseline: 7.0891x; 1.3722x over previous
#include <cuda_runtime.h>
#include <cuda_fp16.h>
#include <math.h>

#define D_MODEL 768
#define NHEAD 12
#define HD 64
#define BATCH 2
#define SEQ 2048
#define MROWS (BATCH*SEQ)   // 4096

// -------- scratch (fp16; no allocations) --------
__device__ __half g_Q[BATCH*NHEAD*SEQ*HD];
__device__ __half g_K[BATCH*NHEAD*SEQ*HD];
__device__ __half g_V[BATCH*NHEAD*SEQ*HD];
__device__ __half g_ctx[MROWS*D_MODEL];
__device__ __half g_xh[MROWS*D_MODEL];
__device__ __half g_Wqh[D_MODEL*D_MODEL];
__device__ __half g_Wkh[D_MODEL*D_MODEL];
__device__ __half g_Wvh[D_MODEL*D_MODEL];
__device__ __half g_Woh[D_MODEL*D_MODEL];

// -------- helpers --------
__device__ __forceinline__ unsigned smem_u32(const void* p) {
    return (unsigned)__cvta_generic_to_shared(p);
}
__device__ __forceinline__ unsigned pack2(float a, float b) {
    __half2 h = __floats2half2_rn(a, b);
    return *reinterpret_cast<unsigned*>(&h);
}
__device__ __forceinline__ float ex2f(float x) {
    float r; asm("ex2.approx.f32 %0, %1;" : "=f"(r) : "f"(x)); return r;
}
__device__ __forceinline__ void ldm4(unsigned& r0, unsigned& r1, unsigned& r2, unsigned& r3,
                                     unsigned addr) {
    asm volatile("ldmatrix.sync.aligned.m8n8.x4.shared.b16 {%0,%1,%2,%3},[%4];"
                 : "=r"(r0), "=r"(r1), "=r"(r2), "=r"(r3) : "r"(addr));
}
__device__ __forceinline__ void ldm4t(unsigned& r0, unsigned& r1, unsigned& r2, unsigned& r3,
                                      unsigned addr) {
    asm volatile("ldmatrix.sync.aligned.m8n8.x4.trans.shared.b16 {%0,%1,%2,%3},[%4];"
                 : "=r"(r0), "=r"(r1), "=r"(r2), "=r"(r3) : "r"(addr));
}
__device__ __forceinline__ void mma16816(float* c, const unsigned* a, unsigned b0, unsigned b1) {
    asm volatile(
        "mma.sync.aligned.m16n8k16.row.col.f32.f16.f16.f32 "
        "{%0,%1,%2,%3},{%4,%5,%6,%7},{%8,%9},{%0,%1,%2,%3};"
        : "+f"(c[0]), "+f"(c[1]), "+f"(c[2]), "+f"(c[3])
        : "r"(a[0]), "r"(a[1]), "r"(a[2]), "r"(a[3]), "r"(b0), "r"(b1));
}
__device__ __forceinline__ void cp16(unsigned dst, const void* src) {
    asm volatile("cp.async.cg.shared.global [%0], [%1], 16;" :: "r"(dst), "l"(src));
}
__device__ __forceinline__ void cp_commit() { asm volatile("cp.async.commit_group;"); }
__device__ __forceinline__ void cp_wait1() { asm volatile("cp.async.wait_group 1;"); }
__device__ __forceinline__ void cp_wait0() { asm volatile("cp.async.wait_group 0;"); }

// ============================================================
// fp32 -> fp16 converter (8 elems/thread)
// ============================================================
__global__ __launch_bounds__(256) void cvt_f2h(const float* __restrict__ src,
                                               __half* __restrict__ dst, int n8)
{
    int i = blockIdx.x * 256 + threadIdx.x;
    if (i >= n8) return;
    float4 a = *(const float4*)&src[i * 8];
    float4 b = *(const float4*)&src[i * 8 + 4];
    uint4 h;
    h.x = pack2(a.x, a.y); h.y = pack2(a.z, a.w);
    h.z = pack2(b.x, b.y); h.w = pack2(b.z, b.w);
    *(uint4*)&dst[i * 8] = h;
}

// ============================================================
// fp16 GEMM (pipelined): out = Xh[M x 768] @ Wh[768 x 768] + bias
// block 64m x 128n, k-slab 32, 2-stage cp.async, 1 sync/slab.
// ============================================================
#define ALD 40
#define BLD 136

template<bool OUT_HALF, bool SCATTER>
__global__ __launch_bounds__(256, 2) void gemm_f16(
    const __half* __restrict__ X, const __half* __restrict__ W,
    const float* __restrict__ bias, void* __restrict__ outp, float oscale)
{
    __shared__ __half As[2][64 * ALD];
    __shared__ __half Bs[2][32 * BLD];

    const int tid = threadIdx.x;
    const int lane = tid & 31;
    const int g = lane >> 2;
    const int t = lane & 3;
    const int wid = tid >> 5;
    const int wm = (wid & 1) * 32;
    const int wn = (wid >> 1) * 32;
    const int row0 = blockIdx.y * 64;
    const int col0 = blockIdx.x * 128;

    float acc[2][4][4];
#pragma unroll
    for (int i = 0; i < 2; i++)
#pragma unroll
        for (int j = 0; j < 4; j++)
#pragma unroll
            for (int k = 0; k < 4; k++) acc[i][j][k] = 0.f;

    const int ar = tid >> 2, ac = (tid & 3) * 8;

    auto submit = [&](int k0, int st) {
        cp16(smem_u32(&As[st][ar * ALD + ac]),
             &X[(size_t)(row0 + ar) * 768 + k0 + ac]);
#pragma unroll
        for (int i = 0; i < 2; i++) {
            int ci = tid + 256 * i;
            int br = ci >> 4, bc = (ci & 15) * 8;
            cp16(smem_u32(&Bs[st][br * BLD + bc]),
                 &W[(size_t)(k0 + br) * 768 + col0 + bc]);
        }
        cp_commit();
    };

    submit(0, 0);
    const int NK = 768 / 32;

    for (int k = 0; k < NK; k++) {
        const int s = k & 1;
        cp_wait0();
        __syncthreads();
        if (k + 1 < NK) submit((k + 1) * 32, s ^ 1);

#pragma unroll
        for (int ks = 0; ks < 2; ks++) {
            unsigned a[2][4];
#pragma unroll
            for (int mt = 0; mt < 2; mt++)
                ldm4(a[mt][0], a[mt][1], a[mt][2], a[mt][3],
                     smem_u32(&As[s][(wm + mt * 16 + (lane & 15)) * ALD +
                                     ks * 16 + ((lane >> 4) << 3)]));
            unsigned b[2][4];
#pragma unroll
            for (int np = 0; np < 2; np++)
                ldm4t(b[np][0], b[np][1], b[np][2], b[np][3],
                      smem_u32(&Bs[s][(ks * 16 + (lane & 7) + ((lane >> 3) & 1) * 8) * BLD +
                                      wn + np * 16 + (lane >> 4) * 8]));
#pragma unroll
            for (int mt = 0; mt < 2; mt++)
#pragma unroll
                for (int np = 0; np < 2; np++) {
                    mma16816(acc[mt][np * 2], a[mt], b[np][0], b[np][1]);
                    mma16816(acc[mt][np * 2 + 1], a[mt], b[np][2], b[np][3]);
                }
        }
        __syncthreads();
    }

#pragma unroll
    for (int nt = 0; nt < 4; nt++) {
        int col = col0 + wn + nt * 8 + 2 * t;
        float b0 = bias[col], b1 = bias[col + 1];
#pragma unroll
        for (int mt = 0; mt < 2; mt++)
#pragma unroll
            for (int hh = 0; hh < 2; hh++) {
                int m = row0 + wm + mt * 16 + g + hh * 8;
                float v0 = (acc[mt][nt][hh * 2] + b0) * oscale;
                float v1 = (acc[mt][nt][hh * 2 + 1] + b1) * oscale;
                if constexpr (OUT_HALF) {
                    __half* oh = (__half*)outp;
                    size_t idx;
                    if constexpr (SCATTER) {
                        int head = col >> 6, d = col & 63;
                        int bb = m >> 11, ss = m & 2047;
                        idx = ((size_t)(bb * NHEAD + head) * SEQ + ss) * HD + d;
                    } else {
                        idx = (size_t)m * 768 + col;
                    }
                    *(__half2*)&oh[idx] = __floats2half2_rn(v0, v1);
                } else {
                    float* of = (float*)outp;
                    float2 o; o.x = v0; o.y = v1;
                    *(float2*)&of[(size_t)m * 768 + col] = o;
                }
            }
    }
}

// ============================================================
// fp16 flash attention: q-tile 128, 8 warps x 16 q-rows,
// 64-key tiles, 3-stage cp.async, base-2 softmax w/ h2exp2.
// Scale (1/8)*log2(e) is folded into the Q projection.
// ============================================================
#define QLD 72
#define KVLD 72

__global__ __launch_bounds__(256, 2) void attn_f16(
    const __half* __restrict__ Qg, const __half* __restrict__ Kg,
    const __half* __restrict__ Vg, __half* __restrict__ ctx)
{
    extern __shared__ __half sm[];
    __half* Qs = sm;                       // [128][QLD]
    __half* KV = sm + 128 * QLD;           // 3 stages x (K[64][KVLD], V[64][KVLD])

    const int tid = threadIdx.x;
    const int lane = tid & 31;
    const int g = lane >> 2;
    const int t = lane & 3;
    const int wid = tid >> 5;
    const int qr = wid * 16;
    const int bh = blockIdx.y;
    const int qt = blockIdx.x;

    const __half* Qp = Qg + ((size_t)bh * SEQ + qt * 128) * HD;
    const __half* Kbase = Kg + (size_t)bh * SEQ * HD;
    const __half* Vbase = Vg + (size_t)bh * SEQ * HD;

    const int NT = SEQ / 64;

    auto submit = [&](int kt, int st) {
        const __half* Kp = Kbase + (size_t)kt * 64 * HD;
        const __half* Vp = Vbase + (size_t)kt * 64 * HD;
        __half* Kd = KV + st * 2 * 64 * KVLD;
        __half* Vd = Kd + 64 * KVLD;
#pragma unroll
        for (int i = 0; i < 2; i++) {
            int ci = tid + 256 * i;
            int row = ci >> 3, c = ci & 7;
            cp16(smem_u32(&Kd[row * KVLD + c * 8]), &Kp[(size_t)row * HD + c * 8]);
            cp16(smem_u32(&Vd[row * KVLD + c * 8]), &Vp[(size_t)row * HD + c * 8]);
        }
        cp_commit();
    };

    // stage Q while first K/V tiles fly
    submit(0, 0);
    submit(1, 1);
#pragma unroll
    for (int i = 0; i < 4; i++) {
        int ci = tid + 256 * i;
        int row = ci >> 3, c = ci & 7;
        *(uint4*)&Qs[row * QLD + c * 8] = *(const uint4*)&Qp[(size_t)row * HD + c * 8];
    }
    __syncthreads();
    unsigned qa[4][4];
#pragma unroll
    for (int ks = 0; ks < 4; ks++)
        ldm4(qa[ks][0], qa[ks][1], qa[ks][2], qa[ks][3],
             smem_u32(&Qs[(qr + (lane & 15)) * QLD + ks * 16 + ((lane >> 4) << 3)]));

    float acc[8][4];
    float rowm[2] = {-1e30f, -1e30f}, rowl[2] = {0.f, 0.f};
#pragma unroll
    for (int i = 0; i < 8; i++)
#pragma unroll
        for (int j = 0; j < 4; j++) acc[i][j] = 0.f;

    for (int kt = 0; kt < NT; kt++) {
        const int s = kt % 3;
        cp_wait1();
        __syncthreads();
        if (kt + 2 < NT) submit(kt + 2, (kt + 2) % 3);

        const __half* Kd = KV + s * 2 * 64 * KVLD;
        const __half* Vd = Kd + 64 * KVLD;

        // ---- scores = Q @ K^T ----
        float sc[8][4];
#pragma unroll
        for (int i = 0; i < 8; i++)
#pragma unroll
            for (int j = 0; j < 4; j++) sc[i][j] = 0.f;

#pragma unroll
        for (int ks = 0; ks < 4; ks++) {
            unsigned kb[4][4];
#pragma unroll
            for (int kp = 0; kp < 4; kp++)
                ldm4(kb[kp][0], kb[kp][1], kb[kp][2], kb[kp][3],
                     smem_u32(&Kd[(kp * 16 + (lane & 15)) * KVLD +
                                  ks * 16 + ((lane >> 4) << 3)]));
#pragma unroll
            for (int kp = 0; kp < 4; kp++) {
                mma16816(sc[kp * 2],     qa[ks], kb[kp][0], kb[kp][2]);
                mma16816(sc[kp * 2 + 1], qa[ks], kb[kp][1], kb[kp][3]);
            }
        }

        // ---- online softmax, base-2 domain ----
        float newm[2], corr[2];
#pragma unroll
        for (int hh = 0; hh < 2; hh++) {
            float mx = -1e30f;
#pragma unroll
            for (int nt = 0; nt < 8; nt++)
                mx = fmaxf(mx, fmaxf(sc[nt][hh * 2], sc[nt][hh * 2 + 1]));
            mx = fmaxf(mx, __shfl_xor_sync(0xffffffffu, mx, 1));
            mx = fmaxf(mx, __shfl_xor_sync(0xffffffffu, mx, 2));
            newm[hh] = fmaxf(rowm[hh], mx);
            corr[hh] = ex2f(rowm[hh] - newm[hh]);
            rowm[hh] = newm[hh];
#pragma unroll
            for (int nt = 0; nt < 8; nt++) {
                acc[nt][hh * 2] *= corr[hh];
                acc[nt][hh * 2 + 1] *= corr[hh];
            }
        }

        // ---- P = exp2(s - m) in fp16x2, direct A-fragments ----
        unsigned ph[4][4];
        float ps0 = 0.f, ps1 = 0.f;
#pragma unroll
        for (int nt = 0; nt < 8; nt++) {
            __half2 e0 = h2exp2(__floats2half2_rn(sc[nt][0] - newm[0], sc[nt][1] - newm[0]));
            __half2 e1 = h2exp2(__floats2half2_rn(sc[nt][2] - newm[1], sc[nt][3] - newm[1]));
            ph[nt >> 1][(nt & 1) * 2]     = *reinterpret_cast<unsigned*>(&e0);
            ph[nt >> 1][(nt & 1) * 2 + 1] = *reinterpret_cast<unsigned*>(&e1);
            float2 f0 = __half22float2(e0);
            float2 f1 = __half22float2(e1);
            ps0 += f0.x + f0.y;
            ps1 += f1.x + f1.y;
        }
        ps0 += __shfl_xor_sync(0xffffffffu, ps0, 1);
        ps0 += __shfl_xor_sync(0xffffffffu, ps0, 2);
        ps1 += __shfl_xor_sync(0xffffffffu, ps1, 1);
        ps1 += __shfl_xor_sync(0xffffffffu, ps1, 2);
        rowl[0] = rowl[0] * corr[0] + ps0;
        rowl[1] = rowl[1] * corr[1] + ps1;

        // ---- acc += P @ V ----
#pragma unroll
        for (int ks = 0; ks < 4; ks++) {
            unsigned vb[4][4];
#pragma unroll
            for (int dp = 0; dp < 4; dp++)
                ldm4t(vb[dp][0], vb[dp][1], vb[dp][2], vb[dp][3],
                      smem_u32(&Vd[(ks * 16 + (lane & 7) + ((lane >> 3) & 1) * 8) * KVLD +
                                   dp * 16 + (lane >> 4) * 8]));
#pragma unroll
            for (int dp = 0; dp < 4; dp++) {
                mma16816(acc[dp * 2],     ph[ks], vb[dp][0], vb[dp][1]);
                mma16816(acc[dp * 2 + 1], ph[ks], vb[dp][2], vb[dp][3]);
            }
        }
    }

    // ---- epilogue ----
    const int bb = bh / NHEAD;
    const int head = bh % NHEAD;
#pragma unroll
    for (int hh = 0; hh < 2; hh++) {
        int q = qt * 128 + qr + g + hh * 8;
        float inv = 1.f / rowl[hh];
#pragma unroll
        for (int nt = 0; nt < 8; nt++) {
            int d = nt * 8 + 2 * t;
            *(__half2*)&ctx[(size_t)(bb * SEQ + q) * D_MODEL + head * HD + d] =
                __floats2half2_rn(acc[nt][hh * 2] * inv, acc[nt][hh * 2 + 1] * inv);
        }
    }
}

// ============================================================
extern "C" void kernel_launch(void* const* d_in, const int* in_sizes, int n_in,
                              void* d_out, int out_size)
{
    const float* x  = (const float*)d_in[0];
    const float* Wq = (const float*)d_in[1];
    const float* bq = (const float*)d_in[2];
    const float* Wk = (const float*)d_in[3];
    const float* bk = (const float*)d_in[4];
    const float* Wv = (const float*)d_in[5];
    const float* bv = (const float*)d_in[6];
    const float* Wo = (const float*)d_in[7];
    const float* bo = (const float*)d_in[8];
    float* out = (float*)d_out;

    __half *Qp, *Kp, *Vp, *ctxp, *xh, *Wqh, *Wkh, *Wvh, *Woh;
    cudaGetSymbolAddress((void**)&Qp, g_Q);
    cudaGetSymbolAddress((void**)&Kp, g_K);
    cudaGetSymbolAddress((void**)&Vp, g_V);
    cudaGetSymbolAddress((void**)&ctxp, g_ctx);
    cudaGetSymbolAddress((void**)&xh, g_xh);
    cudaGetSymbolAddress((void**)&Wqh, g_Wqh);
    cudaGetSymbolAddress((void**)&Wkh, g_Wkh);
    cudaGetSymbolAddress((void**)&Wvh, g_Wvh);
    cudaGetSymbolAddress((void**)&Woh, g_Woh);

    const size_t attn_smem = (size_t)(128 * QLD + 6 * 64 * KVLD) * sizeof(__half);
    cudaFuncSetAttribute(attn_f16, cudaFuncAttributeMaxDynamicSharedMemorySize,
                         (int)attn_smem);

    // fp32 -> fp16 conversions
    const int nX8 = MROWS * D_MODEL / 8, nW8 = D_MODEL * D_MODEL / 8;
    cvt_f2h<<<(nX8 + 255) / 256, 256>>>(x, xh, nX8);
    cvt_f2h<<<(nW8 + 255) / 256, 256>>>(Wq, Wqh, nW8);
    cvt_f2h<<<(nW8 + 255) / 256, 256>>>(Wk, Wkh, nW8);
    cvt_f2h<<<(nW8 + 255) / 256, 256>>>(Wv, Wvh, nW8);
    cvt_f2h<<<(nW8 + 255) / 256, 256>>>(Wo, Woh, nW8);

    dim3 gg(768 / 128, MROWS / 64);    // (6, 64)
    const float QSCALE = 0.125f * 1.4426950408889634f;  // (1/sqrt(hd)) * log2(e)
    gemm_f16<true, true><<<gg, 256>>>(xh, Wqh, bq, Qp, QSCALE);
    gemm_f16<true, true><<<gg, 256>>>(xh, Wkh, bk, Kp, 1.0f);
    gemm_f16<true, true><<<gg, 256>>>(xh, Wvh, bv, Vp, 1.0f);

    dim3 ga(SEQ / 128, BATCH * NHEAD); // (16, 24)
    attn_f16<<<ga, 256, attn_smem>>>(Qp, Kp, Vp, ctxp);

    gemm_f16<false, false><<<gg, 256>>>(ctxp, Woh, bo, out, 1.0f);
}

// round 5
// speedup vs baseline: 8.2340x; 1.1615x over previous
#include <cuda_runtime.h>
#include <cuda_fp16.h>
#include <math.h>

#define D_MODEL 768
#define NHEAD 12
#define HD 64
#define BATCH 2
#define SEQ 2048
#define MROWS (BATCH*SEQ)   // 4096

// -------- scratch (fp16; no allocations) --------
__device__ __half g_Q[BATCH*NHEAD*SEQ*HD];
__device__ __half g_K[BATCH*NHEAD*SEQ*HD];
__device__ __half g_V[BATCH*NHEAD*SEQ*HD];
__device__ __half g_ctx[MROWS*D_MODEL];
__device__ __half g_xh[MROWS*D_MODEL];
__device__ __half g_Wqh[D_MODEL*D_MODEL];
__device__ __half g_Wkh[D_MODEL*D_MODEL];
__device__ __half g_Wvh[D_MODEL*D_MODEL];
__device__ __half g_Woh[D_MODEL*D_MODEL];

// -------- helpers --------
__device__ __forceinline__ unsigned smem_u32(const void* p) {
    return (unsigned)__cvta_generic_to_shared(p);
}
__device__ __forceinline__ unsigned pack2(float a, float b) {
    __half2 h = __floats2half2_rn(a, b);
    return *reinterpret_cast<unsigned*>(&h);
}
__device__ __forceinline__ float ex2f(float x) {
    float r; asm("ex2.approx.f32 %0, %1;" : "=f"(r) : "f"(x)); return r;
}
__device__ __forceinline__ void ldm4(unsigned& r0, unsigned& r1, unsigned& r2, unsigned& r3,
                                     unsigned addr) {
    asm volatile("ldmatrix.sync.aligned.m8n8.x4.shared.b16 {%0,%1,%2,%3},[%4];"
                 : "=r"(r0), "=r"(r1), "=r"(r2), "=r"(r3) : "r"(addr));
}
__device__ __forceinline__ void ldm4t(unsigned& r0, unsigned& r1, unsigned& r2, unsigned& r3,
                                      unsigned addr) {
    asm volatile("ldmatrix.sync.aligned.m8n8.x4.trans.shared.b16 {%0,%1,%2,%3},[%4];"
                 : "=r"(r0), "=r"(r1), "=r"(r2), "=r"(r3) : "r"(addr));
}
__device__ __forceinline__ void mma16816(float* c, const unsigned* a, unsigned b0, unsigned b1) {
    asm volatile(
        "mma.sync.aligned.m16n8k16.row.col.f32.f16.f16.f32 "
        "{%0,%1,%2,%3},{%4,%5,%6,%7},{%8,%9},{%0,%1,%2,%3};"
        : "+f"(c[0]), "+f"(c[1]), "+f"(c[2]), "+f"(c[3])
        : "r"(a[0]), "r"(a[1]), "r"(a[2]), "r"(a[3]), "r"(b0), "r"(b1));
}
__device__ __forceinline__ void cp16(unsigned dst, const void* src) {
    asm volatile("cp.async.cg.shared.global [%0], [%1], 16;" :: "r"(dst), "l"(src));
}
__device__ __forceinline__ void cp_commit() { asm volatile("cp.async.commit_group;"); }
__device__ __forceinline__ void cp_wait1() { asm volatile("cp.async.wait_group 1;"); }
__device__ __forceinline__ void cp_wait0() { asm volatile("cp.async.wait_group 0;"); }

// ============================================================
// fused fp32 -> fp16 conversion of x + all 4 weights
// ============================================================
#define N8X (MROWS*D_MODEL/8)          // 393216
#define N8W (D_MODEL*D_MODEL/8)        // 73728
#define N8TOT (N8X + 4*N8W)            // 688128

__global__ __launch_bounds__(256) void cvt_all(
    const float* __restrict__ x,
    const float* __restrict__ wq, const float* __restrict__ wk,
    const float* __restrict__ wv, const float* __restrict__ wo,
    __half* __restrict__ xh,
    __half* __restrict__ wqh, __half* __restrict__ wkh,
    __half* __restrict__ wvh, __half* __restrict__ woh)
{
    int i = blockIdx.x * 256 + threadIdx.x;
    if (i >= N8TOT) return;
    const float* src;
    __half* dst;
    int off;
    if (i < N8X) { src = x; dst = xh; off = i; }
    else {
        int j = i - N8X;
        int seg = j / N8W;
        off = j - seg * N8W;
        src = (seg == 0) ? wq : (seg == 1) ? wk : (seg == 2) ? wv : wo;
        dst = (seg == 0) ? wqh : (seg == 1) ? wkh : (seg == 2) ? wvh : woh;
    }
    float4 a = *(const float4*)&src[(size_t)off * 8];
    float4 b = *(const float4*)&src[(size_t)off * 8 + 4];
    uint4 h;
    h.x = pack2(a.x, a.y); h.y = pack2(a.z, a.w);
    h.z = pack2(b.x, b.y); h.w = pack2(b.z, b.w);
    *(uint4*)&dst[(size_t)off * 8] = h;
}

// ============================================================
// fp16 GEMM core: 128m x 128n block, k-slab 32, 2-stage cp.async,
// 256 thr = 8 warps (4m x 2n), warp tile 32m x 64n.
// ============================================================
#define ALD 40
#define BLD 136

template<bool OUT_HALF, bool SCATTER>
__device__ __forceinline__ void gemm_body(
    const __half* __restrict__ X, const __half* __restrict__ W,
    const float* __restrict__ bias, void* __restrict__ outp, float oscale,
    int row0, int col0)
{
    __shared__ __half As[2][128 * ALD];
    __shared__ __half Bs[2][32 * BLD];

    const int tid = threadIdx.x;
    const int lane = tid & 31;
    const int g = lane >> 2;
    const int t = lane & 3;
    const int wid = tid >> 5;
    const int wm = (wid & 3) * 32;
    const int wn = (wid >> 2) * 64;

    float acc[2][8][4];
#pragma unroll
    for (int i = 0; i < 2; i++)
#pragma unroll
        for (int j = 0; j < 8; j++)
#pragma unroll
            for (int k = 0; k < 4; k++) acc[i][j][k] = 0.f;

    auto submit = [&](int k0, int st) {
#pragma unroll
        for (int i = 0; i < 2; i++) {
            int ci = tid + 256 * i;
            int ar = ci >> 2, ac = (ci & 3) * 8;
            cp16(smem_u32(&As[st][ar * ALD + ac]),
                 &X[(size_t)(row0 + ar) * 768 + k0 + ac]);
        }
#pragma unroll
        for (int i = 0; i < 2; i++) {
            int ci = tid + 256 * i;
            int br = ci >> 4, bc = (ci & 15) * 8;
            cp16(smem_u32(&Bs[st][br * BLD + bc]),
                 &W[(size_t)(k0 + br) * 768 + col0 + bc]);
        }
        cp_commit();
    };

    submit(0, 0);
    const int NK = 768 / 32;

    for (int k = 0; k < NK; k++) {
        const int s = k & 1;
        cp_wait0();
        __syncthreads();
        if (k + 1 < NK) submit((k + 1) * 32, s ^ 1);

#pragma unroll
        for (int ks = 0; ks < 2; ks++) {
            unsigned a[2][4];
#pragma unroll
            for (int mt = 0; mt < 2; mt++)
                ldm4(a[mt][0], a[mt][1], a[mt][2], a[mt][3],
                     smem_u32(&As[s][(wm + mt * 16 + (lane & 15)) * ALD +
                                     ks * 16 + ((lane >> 4) << 3)]));
            unsigned b[4][4];
#pragma unroll
            for (int np = 0; np < 4; np++)
                ldm4t(b[np][0], b[np][1], b[np][2], b[np][3],
                      smem_u32(&Bs[s][(ks * 16 + (lane & 7) + ((lane >> 3) & 1) * 8) * BLD +
                                      wn + np * 16 + (lane >> 4) * 8]));
#pragma unroll
            for (int mt = 0; mt < 2; mt++)
#pragma unroll
                for (int np = 0; np < 4; np++) {
                    mma16816(acc[mt][np * 2], a[mt], b[np][0], b[np][1]);
                    mma16816(acc[mt][np * 2 + 1], a[mt], b[np][2], b[np][3]);
                }
        }
        __syncthreads();
    }

#pragma unroll
    for (int nt = 0; nt < 8; nt++) {
        int col = col0 + wn + nt * 8 + 2 * t;
        float b0 = bias[col], b1 = bias[col + 1];
#pragma unroll
        for (int mt = 0; mt < 2; mt++)
#pragma unroll
            for (int hh = 0; hh < 2; hh++) {
                int m = row0 + wm + mt * 16 + g + hh * 8;
                float v0 = (acc[mt][nt][hh * 2] + b0) * oscale;
                float v1 = (acc[mt][nt][hh * 2 + 1] + b1) * oscale;
                if constexpr (OUT_HALF) {
                    __half* oh = (__half*)outp;
                    size_t idx;
                    if constexpr (SCATTER) {
                        int head = col >> 6, d = col & 63;
                        int bb = m >> 11, ss = m & 2047;
                        idx = ((size_t)(bb * NHEAD + head) * SEQ + ss) * HD + d;
                    } else {
                        idx = (size_t)m * 768 + col;
                    }
                    *(__half2*)&oh[idx] = __floats2half2_rn(v0, v1);
                } else {
                    float* of = (float*)outp;
                    float2 o; o.x = v0; o.y = v1;
                    *(float2*)&of[(size_t)m * 768 + col] = o;
                }
            }
    }
}

// fused Q/K/V projection: blockIdx.z selects weight/bias/output/scale
__global__ __launch_bounds__(256, 2) void gemm_qkv(
    const __half* __restrict__ X,
    const __half* __restrict__ Wq, const __half* __restrict__ Wk,
    const __half* __restrict__ Wv,
    const float* __restrict__ bq, const float* __restrict__ bk,
    const float* __restrict__ bv,
    __half* __restrict__ Qo, __half* __restrict__ Ko, __half* __restrict__ Vo,
    float qscale)
{
    const int z = blockIdx.z;
    const __half* W = (z == 0) ? Wq : (z == 1) ? Wk : Wv;
    const float* b  = (z == 0) ? bq : (z == 1) ? bk : bv;
    __half* o       = (z == 0) ? Qo : (z == 1) ? Ko : Vo;
    float sc        = (z == 0) ? qscale : 1.0f;
    gemm_body<true, true>(X, W, b, o, sc, blockIdx.y * 128, blockIdx.x * 128);
}

// output projection: fp32 out
__global__ __launch_bounds__(256, 2) void gemm_out(
    const __half* __restrict__ X, const __half* __restrict__ W,
    const float* __restrict__ bias, float* __restrict__ out)
{
    gemm_body<false, false>(X, W, bias, out, 1.0f, blockIdx.y * 128, blockIdx.x * 128);
}

// ============================================================
// fp16 flash attention: q-tile 128, 8 warps x 16 q-rows,
// 64-key tiles, 3-stage cp.async, base-2 softmax w/ h2exp2.
// Scale (1/8)*log2(e) is folded into the Q projection.
// ============================================================
#define QLD 72
#define KVLD 72

__global__ __launch_bounds__(256, 2) void attn_f16(
    const __half* __restrict__ Qg, const __half* __restrict__ Kg,
    const __half* __restrict__ Vg, __half* __restrict__ ctx)
{
    extern __shared__ __half sm[];
    __half* Qs = sm;                       // [128][QLD]
    __half* KV = sm + 128 * QLD;           // 3 stages x (K[64][KVLD], V[64][KVLD])

    const int tid = threadIdx.x;
    const int lane = tid & 31;
    const int g = lane >> 2;
    const int t = lane & 3;
    const int wid = tid >> 5;
    const int qr = wid * 16;
    const int bh = blockIdx.y;
    const int qt = blockIdx.x;

    const __half* Qp = Qg + ((size_t)bh * SEQ + qt * 128) * HD;
    const __half* Kbase = Kg + (size_t)bh * SEQ * HD;
    const __half* Vbase = Vg + (size_t)bh * SEQ * HD;

    const int NT = SEQ / 64;

    auto submit = [&](int kt, int st) {
        const __half* Kp = Kbase + (size_t)kt * 64 * HD;
        const __half* Vp = Vbase + (size_t)kt * 64 * HD;
        __half* Kd = KV + st * 2 * 64 * KVLD;
        __half* Vd = Kd + 64 * KVLD;
#pragma unroll
        for (int i = 0; i < 2; i++) {
            int ci = tid + 256 * i;
            int row = ci >> 3, c = ci & 7;
            cp16(smem_u32(&Kd[row * KVLD + c * 8]), &Kp[(size_t)row * HD + c * 8]);
            cp16(smem_u32(&Vd[row * KVLD + c * 8]), &Vp[(size_t)row * HD + c * 8]);
        }
        cp_commit();
    };

    submit(0, 0);
    submit(1, 1);
#pragma unroll
    for (int i = 0; i < 4; i++) {
        int ci = tid + 256 * i;
        int row = ci >> 3, c = ci & 7;
        *(uint4*)&Qs[row * QLD + c * 8] = *(const uint4*)&Qp[(size_t)row * HD + c * 8];
    }
    __syncthreads();
    unsigned qa[4][4];
#pragma unroll
    for (int ks = 0; ks < 4; ks++)
        ldm4(qa[ks][0], qa[ks][1], qa[ks][2], qa[ks][3],
             smem_u32(&Qs[(qr + (lane & 15)) * QLD + ks * 16 + ((lane >> 4) << 3)]));

    float acc[8][4];
    float rowm[2] = {-1e30f, -1e30f}, rowl[2] = {0.f, 0.f};
#pragma unroll
    for (int i = 0; i < 8; i++)
#pragma unroll
        for (int j = 0; j < 4; j++) acc[i][j] = 0.f;

    for (int kt = 0; kt < NT; kt++) {
        const int s = kt % 3;
        cp_wait1();
        __syncthreads();
        if (kt + 2 < NT) submit(kt + 2, (kt + 2) % 3);

        const __half* Kd = KV + s * 2 * 64 * KVLD;
        const __half* Vd = Kd + 64 * KVLD;

        // ---- scores = Q @ K^T ----
        float sc[8][4];
#pragma unroll
        for (int i = 0; i < 8; i++)
#pragma unroll
            for (int j = 0; j < 4; j++) sc[i][j] = 0.f;

#pragma unroll
        for (int ks = 0; ks < 4; ks++) {
            unsigned kb[4][4];
#pragma unroll
            for (int kp = 0; kp < 4; kp++)
                ldm4(kb[kp][0], kb[kp][1], kb[kp][2], kb[kp][3],
                     smem_u32(&Kd[(kp * 16 + (lane & 15)) * KVLD +
                                  ks * 16 + ((lane >> 4) << 3)]));
#pragma unroll
            for (int kp = 0; kp < 4; kp++) {
                mma16816(sc[kp * 2],     qa[ks], kb[kp][0], kb[kp][2]);
                mma16816(sc[kp * 2 + 1], qa[ks], kb[kp][1], kb[kp][3]);
            }
        }

        // ---- online softmax, base-2 domain ----
        float newm[2], corr[2];
#pragma unroll
        for (int hh = 0; hh < 2; hh++) {
            float mx = -1e30f;
#pragma unroll
            for (int nt = 0; nt < 8; nt++)
                mx = fmaxf(mx, fmaxf(sc[nt][hh * 2], sc[nt][hh * 2 + 1]));
            mx = fmaxf(mx, __shfl_xor_sync(0xffffffffu, mx, 1));
            mx = fmaxf(mx, __shfl_xor_sync(0xffffffffu, mx, 2));
            newm[hh] = fmaxf(rowm[hh], mx);
            corr[hh] = ex2f(rowm[hh] - newm[hh]);
            rowm[hh] = newm[hh];
#pragma unroll
            for (int nt = 0; nt < 8; nt++) {
                acc[nt][hh * 2] *= corr[hh];
                acc[nt][hh * 2 + 1] *= corr[hh];
            }
        }

        // ---- P = exp2(s - m) in fp16x2, direct A-fragments ----
        unsigned ph[4][4];
        float ps0 = 0.f, ps1 = 0.f;
#pragma unroll
        for (int nt = 0; nt < 8; nt++) {
            __half2 e0 = h2exp2(__floats2half2_rn(sc[nt][0] - newm[0], sc[nt][1] - newm[0]));
            __half2 e1 = h2exp2(__floats2half2_rn(sc[nt][2] - newm[1], sc[nt][3] - newm[1]));
            ph[nt >> 1][(nt & 1) * 2]     = *reinterpret_cast<unsigned*>(&e0);
            ph[nt >> 1][(nt & 1) * 2 + 1] = *reinterpret_cast<unsigned*>(&e1);
            float2 f0 = __half22float2(e0);
            float2 f1 = __half22float2(e1);
            ps0 += f0.x + f0.y;
            ps1 += f1.x + f1.y;
        }
        ps0 += __shfl_xor_sync(0xffffffffu, ps0, 1);
        ps0 += __shfl_xor_sync(0xffffffffu, ps0, 2);
        ps1 += __shfl_xor_sync(0xffffffffu, ps1, 1);
        ps1 += __shfl_xor_sync(0xffffffffu, ps1, 2);
        rowl[0] = rowl[0] * corr[0] + ps0;
        rowl[1] = rowl[1] * corr[1] + ps1;

        // ---- acc += P @ V ----
#pragma unroll
        for (int ks = 0; ks < 4; ks++) {
            unsigned vb[4][4];
#pragma unroll
            for (int dp = 0; dp < 4; dp++)
                ldm4t(vb[dp][0], vb[dp][1], vb[dp][2], vb[dp][3],
                      smem_u32(&Vd[(ks * 16 + (lane & 7) + ((lane >> 3) & 1) * 8) * KVLD +
                                   dp * 16 + (lane >> 4) * 8]));
#pragma unroll
            for (int dp = 0; dp < 4; dp++) {
                mma16816(acc[dp * 2],     ph[ks], vb[dp][0], vb[dp][1]);
                mma16816(acc[dp * 2 + 1], ph[ks], vb[dp][2], vb[dp][3]);
            }
        }
    }

    // ---- epilogue ----
    const int bb = bh / NHEAD;
    const int head = bh % NHEAD;
#pragma unroll
    for (int hh = 0; hh < 2; hh++) {
        int q = qt * 128 + qr + g + hh * 8;
        float inv = 1.f / rowl[hh];
#pragma unroll
        for (int nt = 0; nt < 8; nt++) {
            int d = nt * 8 + 2 * t;
            *(__half2*)&ctx[(size_t)(bb * SEQ + q) * D_MODEL + head * HD + d] =
                __floats2half2_rn(acc[nt][hh * 2] * inv, acc[nt][hh * 2 + 1] * inv);
        }
    }
}

// ============================================================
extern "C" void kernel_launch(void* const* d_in, const int* in_sizes, int n_in,
                              void* d_out, int out_size)
{
    const float* x  = (const float*)d_in[0];
    const float* Wq = (const float*)d_in[1];
    const float* bq = (const float*)d_in[2];
    const float* Wk = (const float*)d_in[3];
    const float* bk = (const float*)d_in[4];
    const float* Wv = (const float*)d_in[5];
    const float* bv = (const float*)d_in[6];
    const float* Wo = (const float*)d_in[7];
    const float* bo = (const float*)d_in[8];
    float* out = (float*)d_out;

    __half *Qp, *Kp, *Vp, *ctxp, *xh, *Wqh, *Wkh, *Wvh, *Woh;
    cudaGetSymbolAddress((void**)&Qp, g_Q);
    cudaGetSymbolAddress((void**)&Kp, g_K);
    cudaGetSymbolAddress((void**)&Vp, g_V);
    cudaGetSymbolAddress((void**)&ctxp, g_ctx);
    cudaGetSymbolAddress((void**)&xh, g_xh);
    cudaGetSymbolAddress((void**)&Wqh, g_Wqh);
    cudaGetSymbolAddress((void**)&Wkh, g_Wkh);
    cudaGetSymbolAddress((void**)&Wvh, g_Wvh);
    cudaGetSymbolAddress((void**)&Woh, g_Woh);

    const size_t attn_smem = (size_t)(128 * QLD + 6 * 64 * KVLD) * sizeof(__half);
    cudaFuncSetAttribute(attn_f16, cudaFuncAttributeMaxDynamicSharedMemorySize,
                         (int)attn_smem);

    cvt_all<<<(N8TOT + 255) / 256, 256>>>(x, Wq, Wk, Wv, Wo,
                                          xh, Wqh, Wkh, Wvh, Woh);

    const float QSCALE = 0.125f * 1.4426950408889634f;  // (1/sqrt(hd)) * log2(e)
    dim3 gq(768 / 128, MROWS / 128, 3);   // (6, 32, 3)
    gemm_qkv<<<gq, 256>>>(xh, Wqh, Wkh, Wvh, bq, bk, bv, Qp, Kp, Vp, QSCALE);

    dim3 ga(SEQ / 128, BATCH * NHEAD);    // (16, 24)
    attn_f16<<<ga, 256, attn_smem>>>(Qp, Kp, Vp, ctxp);

    dim3 gg(768 / 128, MROWS / 128);      // (6, 32)
    gemm_out<<<gg, 256>>>(ctxp, Woh, bo, out);
}